// round 17
// baseline (speedup 1.0000x reference)
#include <cuda_runtime.h>
#include <cuda_bf16.h>
#include <cuda_fp16.h>
#include <cstdint>

#define BB 16
#define TT 512
#define LL 128
#define NSTEP 129
#define ENCD 512
#define HD 1024
#define ED 512
#define VD 10000
#define AD 512

#define NBLK 148
#define NTHR 512
#define NWARP (NBLK * (NTHR / 32))

typedef unsigned long long u64;

// ---- scratch (device globals; allocs are forbidden) ----
__device__ float g_encproj[(size_t)BB * TT * AD];
__device__ float g_h0[2][BB * HD];
__device__ float g_h1[2][BB * HD];
__device__ float g_c0[BB * HD];
__device__ float g_c1[BB * HD];
__device__ float g_ctx[2][BB * ENCD];
__device__ float g_dproj[BB * AD];
__device__ float g_aw[BB * TT];
__device__ float g_awsum[BB];
__device__ float g_dcat[(size_t)NSTEP * BB * 1536];
__device__ float g_gates[4096 * BB];          // [gate_row][b], zeroed after each read
__device__ unsigned g_bar;
__device__ volatile unsigned g_gen;

// fp16 LSTM weights (L2-resident): [4096 rows][1024 k] each
#define WSZ ((size_t)4096 * 1024)
__device__ __half g_Wih0h[WSZ];
__device__ __half g_Whh0h[WSZ];
__device__ __half g_Wih1h[WSZ];
__device__ __half g_Whh1h[WSZ];

// fp16 buffers for tensor-core logits GEMM
#define MROWS 2176
#define NPAD 10048
__device__ __half g_Ah[(size_t)MROWS * HD];   // [m][k]
__device__ __half g_Bh[(size_t)HD * NPAD];    // [k][n]

#define XSTR 2056                              // smem X row stride (halves)
#define XSMEM (BB * XSTR * 2)                  // bytes

__device__ __forceinline__ float sigf(float x) { return __fdividef(1.f, 1.f + __expf(-x)); }
__device__ __forceinline__ float tanhf_fast(float x) {
    float z = __expf(2.f * x);
    return 1.f - __fdividef(2.f, z + 1.f);
}
__device__ __forceinline__ float tanh_apx(float x) {
    float r; asm("tanh.approx.f32 %0, %1;" : "=f"(r) : "f"(x)); return r;
}
__device__ __forceinline__ void fma2(u64& acc, u64 a, u64 b) {
    asm("fma.rn.f32x2 %0, %1, %2, %0;" : "+l"(acc) : "l"(a), "l"(b));
}
__device__ __forceinline__ u64 pack2(float lo, float hi) {
    u64 r; asm("mov.b64 %0, {%1, %2};" : "=l"(r) : "f"(lo), "f"(hi)); return r;
}
__device__ __forceinline__ void unpack2(u64 v, float& lo, float& hi) {
    asm("mov.b64 {%0, %1}, %2;" : "=f"(lo), "=f"(hi) : "l"(v));
}

// R5-proven barrier
__device__ __forceinline__ void grid_sync(unsigned& mygen) {
    __syncthreads();
    if (threadIdx.x == 0) {
        unsigned tgt = mygen + 1u;
        __threadfence();
        if (atomicAdd(&g_bar, 1u) == NBLK - 1) {
            g_bar = 0u;
            __threadfence();
            g_gen = tgt;
        } else {
            while (g_gen < tgt) { __nanosleep(64); }
            __threadfence();
        }
    }
    mygen += 1u;
    __syncthreads();
}

__device__ __forceinline__ uint32_t smem_u32(const void* p) {
    uint32_t a;
    asm("{ .reg .u64 t; cvta.to.shared.u64 t, %1; cvt.u32.u64 %0, t; }" : "=r"(a) : "l"(p));
    return a;
}
__device__ __forceinline__ void ldmA4(uint32_t* r, uint32_t addr) {
    asm volatile("ldmatrix.sync.aligned.m8n8.x4.shared.b16 {%0,%1,%2,%3}, [%4];"
                 : "=r"(r[0]), "=r"(r[1]), "=r"(r[2]), "=r"(r[3]) : "r"(addr));
}
__device__ __forceinline__ void ldmBT2(uint32_t* r, uint32_t addr) {
    asm volatile("ldmatrix.sync.aligned.m8n8.x2.trans.shared.b16 {%0,%1}, [%2];"
                 : "=r"(r[0]), "=r"(r[1]) : "r"(addr));
}
__device__ __forceinline__ void mma16816h(float* d, const uint32_t* a, const uint32_t* b) {
    asm volatile(
        "mma.sync.aligned.m16n8k16.row.col.f32.f16.f16.f32 "
        "{%0,%1,%2,%3}, {%4,%5,%6,%7}, {%8,%9}, {%0,%1,%2,%3};"
        : "+f"(d[0]), "+f"(d[1]), "+f"(d[2]), "+f"(d[3])
        : "r"(a[0]), "r"(a[1]), "r"(a[2]), "r"(a[3]), "r"(b[0]), "r"(b[1]));
}

__global__ void init_kernel() {
    int i = blockIdx.x * blockDim.x + threadIdx.x;
    if (i < BB * HD) { g_h0[0][i] = 0.f; g_c0[i] = 0.f; g_h1[0][i] = 0.f; g_c1[i] = 0.f; }
    if (i < BB * ENCD) g_ctx[0][i] = 0.f;
    if (i < 4096 * BB) g_gates[i] = 0.f;
    if (i == 0) { g_bar = 0u; g_gen = 0u; }
    for (size_t j = i; j < (size_t)(MROWS - 2064) * HD; j += (size_t)16384)
        g_Ah[(size_t)2064 * HD + j] = __float2half(0.f);
}

// merged converters
__global__ void conv_all_kernel(const float* __restrict__ W0, const float* __restrict__ W1,
                                const float* __restrict__ W2, const float* __restrict__ W3,
                                const float* __restrict__ Wout) {
    size_t i = (size_t)blockIdx.x * blockDim.x + threadIdx.x;
    if (i < WSZ) {
        g_Wih0h[i] = __float2half(W0[i]);
        g_Whh0h[i] = __float2half(W1[i]);
        g_Wih1h[i] = __float2half(W2[i]);
        g_Whh1h[i] = __float2half(W3[i]);
    }
    if (i < (size_t)HD * NPAD) {
        int n = (int)(i % NPAD);
        float v = (n < VD) ? Wout[(size_t)(i / NPAD) * VD + n] : 0.f;
        g_Bh[i] = __float2half(v);
    }
}

// ===================== persistent recurrent kernel (HMMA LSTM) ================
// stage X (16 x 2048 fp16) into smem; LAYER0: [emb|ctx|h0prev], LAYER1: [h0new|h1prev]
template<int LAYER>
__device__ __forceinline__ void stage_x(
    __half* sX, int t, int tid,
    const int* __restrict__ ys, const float* __restrict__ embed,
    const float* __restrict__ ctxr, const float* __restrict__ ha,
    const float* __restrict__ hb)
{
    for (int p = tid; p < BB * 1024; p += NTHR) {
        const int b = p >> 10;
        const int k = (p & 1023) << 1;
        float2 v;
        if (LAYER == 0) {
            if (k < 512) {
                const int tok = (t == 0) ? 1 : ys[b * LL + (t - 1)];
                v = *(const float2*)(embed + (size_t)tok * ED + k);
            } else if (k < 1024) {
                v = *(const float2*)(ctxr + b * ENCD + (k - 512));
            } else {
                v = *(const float2*)(ha + b * HD + (k - 1024));
            }
        } else {
            if (k < 1024) v = *(const float2*)(ha + b * HD + k);
            else          v = *(const float2*)(hb + b * HD + (k - 1024));
        }
        *(half2*)(sX + b * XSTR + k) = __float22half2_rn(v);
    }
}

// gate mma: 2048 jobs = 512 n-blocks x 4 k-splits(512); partials into g_gates[n][b]
__device__ __forceinline__ void gate_mma(
    const __half* sX, uint32_t sX_b, int gw, int lane,
    const __half* __restrict__ Wih, const __half* __restrict__ Whh)
{
    for (int job = gw; job < 2048; job += NWARP) {
        const int nb = job >> 2;
        const int ks = job & 3;
        const int n0 = nb * 8;
        const __half* W = (ks < 2) ? Wih : Whh;
        const __half* wrow = W + (size_t)(n0 + (lane >> 2)) * 1024 + (ks & 1) * 512 + (lane & 3) * 2;
        const uint32_t abase = sX_b + ((lane & 15) * XSTR + ks * 512 + (lane >> 4) * 8) * 2;
        float d[4] = {0.f, 0.f, 0.f, 0.f};
        #pragma unroll 4
        for (int s = 0; s < 32; ++s) {
            uint32_t a[4], b[2];
            b[0] = *(const uint32_t*)(wrow + s * 16);
            b[1] = *(const uint32_t*)(wrow + s * 16 + 8);
            ldmA4(a, abase + s * 32);   // 16 halves = 32 bytes per k-step
            mma16816h(d, a, b);
        }
        const int m = lane >> 2;
        const int nc = n0 + ((lane & 3) << 1);
        atomicAdd(&g_gates[nc * BB + m], d[0]);
        atomicAdd(&g_gates[(nc + 1) * BB + m], d[1]);
        atomicAdd(&g_gates[nc * BB + m + 8], d[2]);
        atomicAdd(&g_gates[(nc + 1) * BB + m + 8], d[3]);
    }
}

// activation: one thread per (u, b); reads 4 gate rows, zeroes them, updates state
template<int LAYER>
__device__ __forceinline__ void activation(
    int t, int gt, const float* __restrict__ bi,
    float* __restrict__ cbuf, float* __restrict__ hout,
    const float* __restrict__ h0new)
{
    if (gt < BB * HD) {
        const int u = gt >> 4;
        const int b = gt & 15;
        float si = g_gates[u * BB + b] + bi[u];
        float sf = g_gates[(u + 1024) * BB + b] + bi[u + HD];
        float sg = g_gates[(u + 2048) * BB + b] + bi[u + 2 * HD];
        float so = g_gates[(u + 3072) * BB + b] + bi[u + 3 * HD];
        g_gates[u * BB + b] = 0.f;
        g_gates[(u + 1024) * BB + b] = 0.f;
        g_gates[(u + 2048) * BB + b] = 0.f;
        g_gates[(u + 3072) * BB + b] = 0.f;
        const int idx = b * HD + u;
        float c = sigf(sf) * cbuf[idx] + sigf(si) * tanhf_fast(sg);
        cbuf[idx] = c;
        float h = sigf(so) * tanhf_fast(c);
        hout[idx] = h;
        if (LAYER == 1)
            g_dcat[((size_t)t * BB + b) * 1536 + u] = h + h0new[idx];
    }
}

__global__ __launch_bounds__(NTHR, 1) void dec_persistent(
    const float* __restrict__ enc_out, const int* __restrict__ enc_lens,
    const int* __restrict__ ys, const float* __restrict__ embed,
    const float* __restrict__ bi0, const float* __restrict__ bi1,
    const float* __restrict__ Wdec, const float* __restrict__ vatt)
{
    extern __shared__ __half sX[];
    const uint32_t sX_b = smem_u32(sX);
    const int tid = threadIdx.x;
    const int lane = tid & 31;
    const int gw = blockIdx.x * (NTHR / 32) + (tid >> 5);
    const int gt = blockIdx.x * NTHR + tid;
    unsigned mygen = 0;

    for (int t = 0; t < NSTEP; ++t) {
        const int par = t & 1;
        const float* h0r = g_h0[par];
        float* h0w = g_h0[par ^ 1];
        const float* h1r = g_h1[par];
        float* h1w = g_h1[par ^ 1];
        const float* ctxr = g_ctx[par];
        float* ctxw = g_ctx[par ^ 1];

        // P1: stage X0 + gate mma layer0; tail: zero dproj
        stage_x<0>(sX, t, tid, ys, embed, ctxr, h0r, nullptr);
        __syncthreads();
        gate_mma(sX, sX_b, gw, lane, g_Wih0h, g_Whh0h);
        if (gt < BB * AD) g_dproj[gt] = 0.f;
        grid_sync(mygen);

        // P2: activation layer0
        activation<0>(t, gt, bi0, g_c0, h0w, nullptr);
        grid_sync(mygen);

        // P3: stage X1 + gate mma layer1; tail: zero ctxw, dcat ctx-half, awsum
        stage_x<1>(sX, t, tid, ys, embed, ctxr, h0w, h1r);
        __syncthreads();
        gate_mma(sX, sX_b, gw, lane, g_Wih1h, g_Whh1h);
        if (gt < BB * ENCD) {
            ctxw[gt] = 0.f;
            g_dcat[((size_t)t * BB + (gt >> 9)) * 1536 + 1024 + (gt & 511)] = 0.f;
        }
        if (gt < BB) g_awsum[gt] = 0.f;
        grid_sync(mygen);

        // P4: activation layer1 (+ dec residual into dcat)
        activation<1>(t, gt, bi1, g_c1, h1w, h0w);
        grid_sync(mygen);

        // P5: dproj partials
        for (int job = gw; job < 2048; job += NWARP) {
            const int b = job >> 7;
            const int cg = (job >> 3) & 15;
            const int ks = job & 7;
            const int a0 = cg << 5;
            const float* dec = g_dcat + ((size_t)t * BB + b) * 1536 + ks * 128;
            const float* w = Wdec + (size_t)(ks * 128) * AD + a0 + lane;
            float s0 = 0.f, s1 = 0.f, s2 = 0.f, s3 = 0.f;
            #pragma unroll 8
            for (int k = 0; k < 128; k += 4) {
                s0 = fmaf(dec[k], w[(size_t)k * AD], s0);
                s1 = fmaf(dec[k + 1], w[(size_t)(k + 1) * AD], s1);
                s2 = fmaf(dec[k + 2], w[(size_t)(k + 2) * AD], s2);
                s3 = fmaf(dec[k + 3], w[(size_t)(k + 3) * AD], s3);
            }
            atomicAdd(&g_dproj[b * AD + a0 + lane], (s0 + s1) + (s2 + s3));
        }
        grid_sync(mygen);

        // P6: attention scores
        for (int job = gw; job < BB * TT; job += NWARP) {
            const int b = job >> 9, tt = job & (TT - 1);
            const float4* p4 = (const float4*)(g_encproj + (size_t)(b * TT + tt) * AD);
            const float4* d4 = (const float4*)(g_dproj + b * AD);
            const float4* v4 = (const float4*)vatt;
            float s = 0.f;
            #pragma unroll
            for (int i = lane; i < AD / 4; i += 32) {
                float4 p = __ldcs(p4 + i); float4 d = d4[i]; float4 vv = v4[i];
                s = fmaf(vv.x, tanh_apx(p.x + d.x), s);
                s = fmaf(vv.y, tanh_apx(p.y + d.y), s);
                s = fmaf(vv.z, tanh_apx(p.z + d.z), s);
                s = fmaf(vv.w, tanh_apx(p.w + d.w), s);
            }
            #pragma unroll
            for (int off = 16; off > 0; off >>= 1) s += __shfl_xor_sync(0xffffffffu, s, off);
            if (lane == 0) {
                float w = (tt < enc_lens[b]) ? __expf(s) : 0.f;
                g_aw[b * TT + tt] = w;
                if (w != 0.f) atomicAdd(&g_awsum[b], w);
            }
        }
        grid_sync(mygen);

        // P7: ctx partials
        for (int job = gw; job < 2048; job += NWARP) {
            const int b = job >> 7;
            const int cg = (job >> 3) & 15;
            const int ts = job & 7;
            const int col = (cg << 5) + lane;
            const float inv = __fdividef(1.f, g_awsum[b]);
            const float* ao = g_aw + b * TT + ts * 64;
            const float* eo = enc_out + (size_t)b * TT * ENCD + (size_t)(ts * 64) * ENCD + col;
            float s0 = 0.f, s1 = 0.f;
            #pragma unroll 8
            for (int tt = 0; tt < 64; tt += 2) {
                s0 = fmaf(ao[tt], __ldcs(eo + (size_t)tt * ENCD), s0);
                s1 = fmaf(ao[tt + 1], __ldcs(eo + (size_t)(tt + 1) * ENCD), s1);
            }
            float cv = (s0 + s1) * inv;
            atomicAdd(&ctxw[b * ENCD + col], cv);
            atomicAdd(&g_dcat[((size_t)t * BB + b) * 1536 + 1024 + col], cv);
        }
        grid_sync(mygen);
    }
}

// ---- tiled fp32 GEMM (FFMA2). mode 0: plain; mode 3: tanh + fp16 store to g_Ah ----
#define GBM 128
#define GBN 64
#define GBK 16

__global__ __launch_bounds__(256) void gemm_kernel(
    const float* __restrict__ Am, const float* __restrict__ Bm,
    const float* __restrict__ bias, float* __restrict__ Cm,
    int M, int N, int K, int mode)
{
    __shared__ float As[GBK][GBM + 4];
    __shared__ float Bs[GBK][GBN];
    const int tid = threadIdx.x;
    const int tx = tid & 15, ty = tid >> 4;
    const int n0 = blockIdx.x * GBN;
    const int m0 = blockIdx.y * GBM;
    u64 acc2[8][2];
    #pragma unroll
    for (int r = 0; r < 8; r++) { acc2[r][0] = 0ull; acc2[r][1] = 0ull; }

    for (int k0 = 0; k0 < K; k0 += GBK) {
        #pragma unroll
        for (int i = tid; i < (GBM * GBK) / 4; i += 256) {
            int row = i >> 2, kq = (i & 3) << 2;
            float4 v = make_float4(0.f, 0.f, 0.f, 0.f);
            int gm = m0 + row;
            if (gm < M) v = *(const float4*)(Am + (size_t)gm * K + k0 + kq);
            As[kq][row] = v.x; As[kq + 1][row] = v.y; As[kq + 2][row] = v.z; As[kq + 3][row] = v.w;
        }
        {
            int row = tid >> 4, nq = (tid & 15) << 2;
            float4 v = make_float4(0.f, 0.f, 0.f, 0.f);
            if (n0 + nq < N) v = *(const float4*)(Bm + (size_t)(k0 + row) * N + n0 + nq);
            *(float4*)&Bs[row][nq] = v;
        }
        __syncthreads();
        #pragma unroll
        for (int k = 0; k < GBK; k++) {
            float4 bv = *(const float4*)&Bs[k][tx << 2];
            u64 b01 = pack2(bv.x, bv.y);
            u64 b23 = pack2(bv.z, bv.w);
            #pragma unroll
            for (int r = 0; r < 8; r++) {
                float a = As[k][(ty << 3) + r];
                u64 aa = pack2(a, a);
                fma2(acc2[r][0], aa, b01);
                fma2(acc2[r][1], aa, b23);
            }
        }
        __syncthreads();
    }
    #pragma unroll
    for (int r = 0; r < 8; r++) {
        int m = m0 + (ty << 3) + r;
        if (m >= M) continue;
        float av[4];
        unpack2(acc2[r][0], av[0], av[1]);
        unpack2(acc2[r][1], av[2], av[3]);
        #pragma unroll
        for (int c = 0; c < 4; c++) {
            int n = n0 + (tx << 2) + c;
            if (n >= N) continue;
            float v = av[c] + bias[n];
            if (mode == 3) {
                g_Ah[(size_t)m * HD + n] = __float2half(tanhf_fast(v));
            } else {
                Cm[(size_t)m * N + n] = v;
            }
        }
    }
}

// ======================= fp16 mma.sync logits GEMM ============================
#define ASTR 40
#define BSTR 72

__global__ __launch_bounds__(256) void wout_mma_kernel(const float* __restrict__ bias,
                                                       float* __restrict__ out)
{
    __shared__ __half sA[128 * ASTR];
    __shared__ __half sB[32 * BSTR];
    const int tid = threadIdx.x;
    const int lane = tid & 31;
    const int w = tid >> 5;
    const int mwarp = w & 3, nwarp = w >> 2;
    const int n0 = blockIdx.x * 64;
    const int m0 = blockIdx.y * 128;

    const uint32_t sA_b = smem_u32(sA), sB_b = smem_u32(sB);
    const uint32_t aoff = ((mwarp * 32 + (lane & 15)) * ASTR + (lane >> 4) * 8) * 2;
    const uint32_t boff = ((lane & 15) * BSTR + nwarp * 32) * 2;

    float d[2][4][4];
    #pragma unroll
    for (int mt = 0; mt < 2; ++mt)
        #pragma unroll
        for (int nt = 0; nt < 4; ++nt)
            #pragma unroll
            for (int i = 0; i < 4; ++i) d[mt][nt][i] = 0.f;

    for (int kc = 0; kc < 32; ++kc) {
        const int kb = kc * 32;
        #pragma unroll
        for (int i = tid; i < 512; i += 256) {
            const int row = i >> 2, kq = (i & 3) << 3;
            *(float4*)((char*)sA + (row * ASTR + kq) * 2) =
                *(const float4*)(g_Ah + (size_t)(m0 + row) * HD + kb + kq);
        }
        {
            const int row = tid >> 3, nq = (tid & 7) << 3;
            *(float4*)((char*)sB + (row * BSTR + nq) * 2) =
                *(const float4*)(g_Bh + (size_t)(kb + row) * NPAD + n0 + nq);
        }
        __syncthreads();

        #pragma unroll
        for (int ks = 0; ks < 2; ++ks) {
            uint32_t ah[2][4], bh[4][2];
            #pragma unroll
            for (int mt = 0; mt < 2; ++mt)
                ldmA4(ah[mt], sA_b + aoff + (mt * 16 * ASTR + ks * 16) * 2);
            #pragma unroll
            for (int nt = 0; nt < 4; ++nt)
                ldmBT2(bh[nt], sB_b + boff + (ks * 16 * BSTR + nt * 8) * 2);
            #pragma unroll
            for (int mt = 0; mt < 2; ++mt)
                #pragma unroll
                for (int nt = 0; nt < 4; ++nt)
                    mma16816h(d[mt][nt], ah[mt], bh[nt]);
        }
        __syncthreads();
    }

    const int grp = lane >> 2, tig = lane & 3;
    #pragma unroll
    for (int mt = 0; mt < 2; ++mt) {
        #pragma unroll
        for (int rr = 0; rr < 2; ++rr) {
            const int m = m0 + mwarp * 32 + mt * 16 + grp + rr * 8;
            if (m >= NSTEP * BB) continue;
            const int bb = m & 15, tt = m >> 4;
            float* orow = out + ((size_t)bb * NSTEP + tt) * VD;
            #pragma unroll
            for (int nt = 0; nt < 4; ++nt) {
                const int n = n0 + nwarp * 32 + nt * 8 + tig * 2;
                if (n < VD) {
                    orow[n] = d[mt][nt][rr * 2 + 0] + bias[n];
                    orow[n + 1] = d[mt][nt][rr * 2 + 1] + bias[n + 1];
                }
            }
        }
    }
}

extern "C" void kernel_launch(void* const* d_in, const int* in_sizes, int n_in,
                              void* d_out, int out_size)
{
    const float* enc_out  = (const float*)d_in[0];
    const int*   enc_lens = (const int*)d_in[1];
    const int*   ys       = (const int*)d_in[2];
    const float* embed    = (const float*)d_in[3];
    const float* Wih0     = (const float*)d_in[4];
    const float* Whh0     = (const float*)d_in[5];
    const float* b0       = (const float*)d_in[6];
    const float* Wih1     = (const float*)d_in[7];
    const float* Whh1     = (const float*)d_in[8];
    const float* b1       = (const float*)d_in[9];
    const float* W_enc    = (const float*)d_in[10];
    const float* b_att    = (const float*)d_in[11];
    const float* v_att    = (const float*)d_in[12];
    const float* W_dec    = (const float*)d_in[13];
    const float* W_bn     = (const float*)d_in[14];
    const float* b_bn     = (const float*)d_in[15];
    const float* W_out    = (const float*)d_in[16];
    const float* b_out    = (const float*)d_in[17];
    float* out = (float*)d_out;

    float *p_encproj, *p_dcat;
    cudaGetSymbolAddress((void**)&p_encproj, g_encproj);
    cudaGetSymbolAddress((void**)&p_dcat, g_dcat);

    init_kernel<<<(4096 * BB + 255) / 256, 256>>>();

    {
        size_t tot = (size_t)HD * NPAD;
        conv_all_kernel<<<(unsigned)((tot + 255) / 256), 256>>>(Wih0, Whh0, Wih1, Whh1, W_out);
    }

    {
        dim3 grid(AD / GBN, (BB * TT + GBM - 1) / GBM);
        gemm_kernel<<<grid, 256>>>(enc_out, W_enc, b_att, p_encproj, BB * TT, AD, ENCD, 0);
    }

    cudaFuncSetAttribute(dec_persistent, cudaFuncAttributeMaxDynamicSharedMemorySize, XSMEM);
    dec_persistent<<<NBLK, NTHR, XSMEM>>>(enc_out, enc_lens, ys, embed, b0, b1, W_dec, v_att);

    {
        dim3 grid(HD / GBN, (NSTEP * BB + GBM - 1) / GBM);
        gemm_kernel<<<grid, 256>>>(p_dcat, W_bn, b_bn, p_dcat /*unused*/, NSTEP * BB, HD, 1536, 3);
    }

    {
        dim3 grid(NPAD / 64, MROWS / 128);
        wout_mma_kernel<<<grid, 256>>>(b_out, out);
    }
    (void)in_sizes; (void)n_in; (void)out_size;
}